// round 15
// baseline (speedup 1.0000x reference)
#include <cuda_runtime.h>
#include <stdint.h>
#include <math.h>

// Field_64682207478165: instant-NGP hash-grid (L=16, T=2^19, F=2) + MLP 35->32->32->1 (ELU)
// Morton counting sort (64^3) + fused encode/MLP (FFMA2 packed).
// Gather: x-corner pairs merged into LDG.128 (hash idx0^idx1==1 when ix even) with a
// predicated LDG.64 fallback for odd ix -> ~25% fewer l1tex wavefronts on high levels.

#define NLVL  16
#define TSZ   (1u << 19)
#define HID   32
#define NFEAT 35
#define NB    (1 << 18)      // 64^3 Morton buckets @ 1/128 granularity over [0.5,1)
#define MAXN  2097152

typedef unsigned int u32;
typedef unsigned long long u64;

struct LevelScales { float s[NLVL]; };

__device__ float4 g_xs[MAXN];     // sorted (xn0, xn1, xn2, idx-as-bits)
__device__ u32    g_hist[NB];
__device__ u32    g_bsum[NB / 1024];

// ---- packed f32x2 helpers ----
__device__ __forceinline__ u64 fma2(u64 a, u64 b, u64 c) {
    u64 d; asm("fma.rn.f32x2 %0, %1, %2, %3;" : "=l"(d) : "l"(a), "l"(b), "l"(c)); return d;
}
__device__ __forceinline__ u64 pk2(float f) {           // (f, f)
    u64 r; asm("mov.b64 %0, {%1, %1};" : "=l"(r) : "f"(f)); return r;
}
__device__ __forceinline__ void unpk(u64 v, float& a, float& b) {
    asm("mov.b64 {%0, %1}, %2;" : "=f"(a), "=f"(b) : "l"(v));
}

// predicated 8B gather: inactive lanes keep fallback, issue NO memory request.
// Hand-written @p load avoids ptxas BSSY/BSYNC divergence overhead.
__device__ __forceinline__ float2 cond_ldg(const float2* a, u32 pred, float2 fb) {
    float rx = fb.x, ry = fb.y;
    asm("{\n\t"
        ".reg .pred p;\n\t"
        "setp.ne.u32 p, %2, 0;\n\t"
        "@p ld.global.nc.v2.f32 {%0, %1}, [%3];\n\t"
        "}"
        : "+f"(rx), "+f"(ry) : "r"(pred), "l"(a));
    return make_float2(rx, ry);
}

__device__ __forceinline__ u32 expand3(u32 v) {
    v &= 0x3FFu;
    v = (v | (v << 16)) & 0x30000FFu;
    v = (v | (v << 8))  & 0x300F00Fu;
    v = (v | (v << 4))  & 0x30C30C3u;
    v = (v | (v << 2))  & 0x9249249u;
    return v;
}

__device__ __forceinline__ u32 bucket_key(float xn0, float xn1, float xn2) {
    int ix = (int)((xn0 - 0.5f) * 128.0f);
    int iy = (int)((xn1 - 0.5f) * 128.0f);
    int iz = (int)((xn2 - 0.5f) * 128.0f);
    ix = min(63, max(0, ix)); iy = min(63, max(0, iy)); iz = min(63, max(0, iz));
    return expand3((u32)ix) | (expand3((u32)iy) << 1) | (expand3((u32)iz) << 2);
}

__global__ void zero_hist_kernel() {
    int i = blockIdx.x * blockDim.x + threadIdx.x;
    if (i < NB) g_hist[i] = 0u;
}

__global__ void hist_kernel(const float* __restrict__ x, int n) {
    int i = blockIdx.x * blockDim.x + threadIdx.x;
    if (i >= n) return;
    const float xn0 = (x[3*i+0] + 1.0f) * 0.5f;
    const float xn1 = (x[3*i+1] + 1.0f) * 0.5f;
    const float xn2 = (x[3*i+2] + 1.0f) * 0.5f;
    atomicAdd(&g_hist[bucket_key(xn0, xn1, xn2)], 1u);
}

__global__ void scan1_kernel() {   // in-block exclusive scan + block total
    __shared__ u32 s[1024];
    const int tid = threadIdx.x;
    const int idx = blockIdx.x * 1024 + tid;
    const u32 v = g_hist[idx];
    s[tid] = v;
    __syncthreads();
    #pragma unroll
    for (int off = 1; off < 1024; off <<= 1) {
        u32 t = (tid >= off) ? s[tid - off] : 0u;
        __syncthreads();
        s[tid] += t;
        __syncthreads();
    }
    g_hist[idx] = s[tid] - v;
    if (tid == 1023) g_bsum[blockIdx.x] = s[1023];
}

__global__ void scan2_kernel() {   // exclusive scan of block sums
    __shared__ u32 s[NB / 1024];
    const int tid = threadIdx.x;
    const u32 v = g_bsum[tid];
    s[tid] = v;
    __syncthreads();
    #pragma unroll
    for (int off = 1; off < NB / 1024; off <<= 1) {
        u32 t = (tid >= off) ? s[tid - off] : 0u;
        __syncthreads();
        s[tid] += t;
        __syncthreads();
    }
    g_bsum[tid] = s[tid] - v;
}

__global__ void scan3_kernel() {
    const int idx = blockIdx.x * 1024 + threadIdx.x;
    g_hist[idx] += g_bsum[blockIdx.x];
}

__global__ void scatter_kernel(const float* __restrict__ x, int n) {
    int i = blockIdx.x * blockDim.x + threadIdx.x;
    if (i >= n) return;
    const float xn0 = (x[3*i+0] + 1.0f) * 0.5f;
    const float xn1 = (x[3*i+1] + 1.0f) * 0.5f;
    const float xn2 = (x[3*i+2] + 1.0f) * 0.5f;
    const u32 pos = atomicAdd(&g_hist[bucket_key(xn0, xn1, xn2)], 1u);
    g_xs[pos] = make_float4(xn0, xn1, xn2, __int_as_float(i));
}

template<bool SORTED>
__global__ __launch_bounds__(256, 3) void field_kernel(
    const float* __restrict__ x,
    const float* __restrict__ table,
    const float* __restrict__ W0,
    const float* __restrict__ b0,
    const float* __restrict__ W1,
    const float* __restrict__ b1,
    const float* __restrict__ Wout,
    const float* __restrict__ bout,
    float* __restrict__ out,
    int n, LevelScales sc)
{
    __shared__ __align__(16) float sW0[NFEAT * HID];
    __shared__ __align__(16) float sW1[HID * HID];
    __shared__ __align__(16) float sB0[HID];
    __shared__ __align__(16) float sB1[HID];
    __shared__ __align__(16) float sWo[HID];
    __shared__ float sBo;

    const int tid = threadIdx.x;
    for (int i = tid; i < NFEAT * HID; i += 256) sW0[i] = W0[i];
    for (int i = tid; i < HID * HID;   i += 256) sW1[i] = W1[i];
    if (tid < HID) { sB0[tid] = b0[tid]; sB1[tid] = b1[tid]; sWo[tid] = Wout[tid]; }
    if (tid == 0) sBo = bout[0];
    __syncthreads();

    const int i = blockIdx.x * 256 + tid;
    if (i >= n) return;

    float xn0, xn1, xn2;
    int oidx;
    if (SORTED) {
        const float4 p = g_xs[i];
        xn0 = p.x; xn1 = p.y; xn2 = p.z; oidx = __float_as_int(p.w);
    } else {
        xn0 = (x[3*i+0] + 1.0f) * 0.5f;
        xn1 = (x[3*i+1] + 1.0f) * 0.5f;
        xn2 = (x[3*i+2] + 1.0f) * 0.5f;
        oidx = i;
    }

    const u32 P1 = 2654435761u, P2 = 805459861u;
    const u32 msk = TSZ - 1u;

    // ---- h1 (packed pairs): h1 = b0 + xn0*W0[0,:] + xn1*W0[1,:] + xn2*W0[2,:] ----
    u64 h1p[HID/2];
    {
        const u64 x0p = pk2(xn0), x1p = pk2(xn1), x2p = pk2(xn2);
        #pragma unroll
        for (int q = 0; q < 8; ++q) {
            const ulonglong2 bb = *(const ulonglong2*)&sB0[4*q];
            const ulonglong2 w0 = *(const ulonglong2*)&sW0[0*HID + 4*q];
            const ulonglong2 w1 = *(const ulonglong2*)&sW0[1*HID + 4*q];
            const ulonglong2 w2 = *(const ulonglong2*)&sW0[2*HID + 4*q];
            h1p[2*q]   = fma2(x2p, w2.x, fma2(x1p, w1.x, fma2(x0p, w0.x, bb.x)));
            h1p[2*q+1] = fma2(x2p, w2.y, fma2(x1p, w1.y, fma2(x0p, w0.y, bb.y)));
        }
    }

    #pragma unroll
    for (int l = 0; l < NLVL; ++l) {
        const float s = sc.s[l];
        const float px = xn0 * s, py = xn1 * s, pz = xn2 * s;
        const float f0 = floorf(px), f1 = floorf(py), f2 = floorf(pz);
        const float wx = px - f0, wy = py - f1, wz = pz - f2;
        const u32 ix = (u32)f0, iy = (u32)f1, iz = (u32)f2;

        const u32 hx0 = ix,      hx1 = ix + 1u;
        const u32 hy0 = iy * P1, hy1 = (iy + 1u) * P1;
        const u32 hz0 = iz * P2, hz1 = (iz + 1u) * P2;
        const u32 oddx = ix & 1u;   // when 0: corner pair {q, q^1} sits in one 16B slot

        const float2* __restrict__ tb = ((const float2*)table) + (size_t)l * TSZ;

        // one (y,z)-combo: LDG.128 covers corner x0 (always) and x1 (iff ix even);
        // odd-ix lanes fetch x1 with a predicated LDG.64 (no BSSY, ~half lanes active).
        #define PAIR_LOAD(MYZ, G0, G1)                                             \
            {                                                                      \
                const u32 q_  = (hx0 ^ (MYZ)) & msk;                               \
                const u32 qa_ = q_ & ~1u;                                          \
                const float4 pk_ = __ldg((const float4*)(tb + qa_));               \
                const float2 e0_ = make_float2(pk_.x, pk_.y);                      \
                const float2 e1_ = make_float2(pk_.z, pk_.w);                      \
                const bool qb_ = (q_ & 1u) != 0u;                                  \
                G0 = qb_ ? e1_ : e0_;                                              \
                const float2 fb_ = qb_ ? e0_ : e1_;                                \
                const u32 r_ = (hx1 ^ (MYZ)) & msk;                                \
                G1 = cond_ldg(tb + r_, oddx, fb_);                                 \
            }

        float2 g000, g100, g010, g110, g001, g101, g011, g111;
        PAIR_LOAD(hy0 ^ hz0, g000, g100);
        PAIR_LOAD(hy1 ^ hz0, g010, g110);
        PAIR_LOAD(hy0 ^ hz1, g001, g101);
        PAIR_LOAD(hy1 ^ hz1, g011, g111);
        #undef PAIR_LOAD

        const float ux = 1.0f - wx, uy = 1.0f - wy, uz = 1.0f - wz;
        const float w000 = ux*uy*uz, w100 = wx*uy*uz, w010 = ux*wy*uz, w110 = wx*wy*uz;
        const float w001 = ux*uy*wz, w101 = wx*uy*wz, w011 = ux*wy*wz, w111 = wx*wy*wz;

        float a0 = w000 * g000.x, a1 = w000 * g000.y;
        a0 = fmaf(w100, g100.x, a0); a1 = fmaf(w100, g100.y, a1);
        a0 = fmaf(w010, g010.x, a0); a1 = fmaf(w010, g010.y, a1);
        a0 = fmaf(w110, g110.x, a0); a1 = fmaf(w110, g110.y, a1);
        a0 = fmaf(w001, g001.x, a0); a1 = fmaf(w001, g001.y, a1);
        a0 = fmaf(w101, g101.x, a0); a1 = fmaf(w101, g101.y, a1);
        a0 = fmaf(w011, g011.x, a0); a1 = fmaf(w011, g011.y, a1);
        a0 = fmaf(w111, g111.x, a0); a1 = fmaf(w111, g111.y, a1);

        // h1 += a0*W0[k,:] + a1*W0[k+1,:]  (packed over j-pairs; per-component order preserved)
        const int k = 3 + 2*l;
        const u64 a0p = pk2(a0), a1p = pk2(a1);
        const float* __restrict__ r0 = &sW0[k * HID];
        const float* __restrict__ r1 = &sW0[(k+1) * HID];
        #pragma unroll
        for (int q = 0; q < 8; ++q) {
            const ulonglong2 w0 = *(const ulonglong2*)(r0 + 4*q);
            const ulonglong2 w1 = *(const ulonglong2*)(r1 + 4*q);
            h1p[2*q]   = fma2(a1p, w1.x, fma2(a0p, w0.x, h1p[2*q]));
            h1p[2*q+1] = fma2(a1p, w1.y, fma2(a0p, w0.y, h1p[2*q+1]));
        }
    }

    // ---- ELU(h1), unpack to scalars ----
    float h1s[HID];
    #pragma unroll
    for (int q = 0; q < HID/2; ++q) {
        float a, b; unpk(h1p[q], a, b);
        h1s[2*q]   = (a > 0.0f) ? a : (__expf(a) - 1.0f);
        h1s[2*q+1] = (b > 0.0f) ? b : (__expf(b) - 1.0f);
    }

    // ---- h2 = elu(h1 @ W1 + b1), packed ----
    u64 h2p[HID/2];
    #pragma unroll
    for (int q = 0; q < 8; ++q) {
        const ulonglong2 bb = *(const ulonglong2*)&sB1[4*q];
        h2p[2*q] = bb.x; h2p[2*q+1] = bb.y;
    }
    #pragma unroll
    for (int k = 0; k < HID; ++k) {
        const u64 fp = pk2(h1s[k]);
        const float* __restrict__ row = &sW1[k * HID];
        #pragma unroll
        for (int q = 0; q < 8; ++q) {
            const ulonglong2 w = *(const ulonglong2*)(row + 4*q);
            h2p[2*q]   = fma2(fp, w.x, h2p[2*q]);
            h2p[2*q+1] = fma2(fp, w.y, h2p[2*q+1]);
        }
    }

    // ---- out = elu(h2) . Wout + bout (scalar, sequential order preserved) ----
    float acc = sBo;
    #pragma unroll
    for (int q = 0; q < HID/2; ++q) {
        float a, b; unpk(h2p[q], a, b);
        a = (a > 0.0f) ? a : (__expf(a) - 1.0f);
        b = (b > 0.0f) ? b : (__expf(b) - 1.0f);
        acc = fmaf(a, sWo[2*q], acc);
        acc = fmaf(b, sWo[2*q+1], acc);
    }

    out[oidx] = acc;
}

extern "C" void kernel_launch(void* const* d_in, const int* in_sizes, int n_in,
                              void* d_out, int out_size)
{
    const float* x     = (const float*)d_in[0];
    const float* table = (const float*)d_in[1];
    const float* W0    = (const float*)d_in[2];
    const float* b0    = (const float*)d_in[3];
    const float* W1    = (const float*)d_in[4];
    const float* b1    = (const float*)d_in[5];
    const float* Wout  = (const float*)d_in[6];
    const float* bout  = (const float*)d_in[7];
    float* out = (float*)d_out;

    const int n = in_sizes[0] / 3;

    LevelScales sc;
    const double B = exp(log(512.0 / 16.0) / 15.0);   // 2^(1/3)
    for (int l = 0; l < NLVL; ++l)
        sc.s[l] = (float)(16.0 * pow(B, (double)l) - 1.0);

    const int blocks = (n + 255) / 256;

    if (n <= MAXN) {
        zero_hist_kernel<<<NB / 1024, 1024>>>();
        hist_kernel<<<blocks, 256>>>(x, n);
        scan1_kernel<<<NB / 1024, 1024>>>();
        scan2_kernel<<<1, NB / 1024>>>();
        scan3_kernel<<<NB / 1024, 1024>>>();
        scatter_kernel<<<blocks, 256>>>(x, n);
        field_kernel<true><<<blocks, 256>>>(x, table, W0, b0, W1, b1, Wout, bout, out, n, sc);
    } else {
        field_kernel<false><<<blocks, 256>>>(x, table, W0, b0, W1, b1, Wout, bout, out, n, sc);
    }
}

// round 16
// speedup vs baseline: 1.0361x; 1.0361x over previous
#include <cuda_runtime.h>
#include <stdint.h>
#include <math.h>

// Field_64682207478165: instant-NGP hash-grid (L=16, T=2^19, F=2) + MLP 35->32->32->1 (ELU)
// Morton counting sort (64^3 buckets) for warp spatial locality + fused encode/MLP
// with packed f32x2 FFMA2 MLP. Sort pipeline trimmed: hist -> scan1 -> scan2 -> scatter
// (scatter adds block offsets; field kernel re-zeroes the histogram for the next replay).

#define NLVL  16
#define TSZ   (1u << 19)
#define HID   32
#define NFEAT 35
#define NB    (1 << 18)      // 64^3 Morton buckets @ 1/128 granularity over [0.5,1)
#define MAXN  2097152

typedef unsigned int u32;
typedef unsigned long long u64;

struct LevelScales { float s[NLVL]; };

__device__ float4 g_xs[MAXN];     // sorted (xn0, xn1, xn2, idx-as-bits)
__device__ u32    g_hist[NB];     // zero-initialized at load; re-zeroed by field_kernel
__device__ u32    g_bsum[NB / 1024];

// ---- packed f32x2 helpers ----
__device__ __forceinline__ u64 fma2(u64 a, u64 b, u64 c) {
    u64 d; asm("fma.rn.f32x2 %0, %1, %2, %3;" : "=l"(d) : "l"(a), "l"(b), "l"(c)); return d;
}
__device__ __forceinline__ u64 pk2(float f) {           // (f, f)
    u64 r; asm("mov.b64 %0, {%1, %1};" : "=l"(r) : "f"(f)); return r;
}
__device__ __forceinline__ void unpk(u64 v, float& a, float& b) {
    asm("mov.b64 {%0, %1}, %2;" : "=f"(a), "=f"(b) : "l"(v));
}

__device__ __forceinline__ u32 expand3(u32 v) {
    v &= 0x3FFu;
    v = (v | (v << 16)) & 0x30000FFu;
    v = (v | (v << 8))  & 0x300F00Fu;
    v = (v | (v << 4))  & 0x30C30C3u;
    v = (v | (v << 2))  & 0x9249249u;
    return v;
}

__device__ __forceinline__ u32 bucket_key(float xn0, float xn1, float xn2) {
    int ix = (int)((xn0 - 0.5f) * 128.0f);
    int iy = (int)((xn1 - 0.5f) * 128.0f);
    int iz = (int)((xn2 - 0.5f) * 128.0f);
    ix = min(63, max(0, ix)); iy = min(63, max(0, iy)); iz = min(63, max(0, iz));
    return expand3((u32)ix) | (expand3((u32)iy) << 1) | (expand3((u32)iz) << 2);
}

__global__ void hist_kernel(const float* __restrict__ x, int n) {
    int i = blockIdx.x * blockDim.x + threadIdx.x;
    if (i >= n) return;
    const float xn0 = (x[3*i+0] + 1.0f) * 0.5f;
    const float xn1 = (x[3*i+1] + 1.0f) * 0.5f;
    const float xn2 = (x[3*i+2] + 1.0f) * 0.5f;
    atomicAdd(&g_hist[bucket_key(xn0, xn1, xn2)], 1u);
}

__global__ void scan1_kernel() {   // in-block exclusive scan + block total
    __shared__ u32 s[1024];
    const int tid = threadIdx.x;
    const int idx = blockIdx.x * 1024 + tid;
    const u32 v = g_hist[idx];
    s[tid] = v;
    __syncthreads();
    #pragma unroll
    for (int off = 1; off < 1024; off <<= 1) {
        u32 t = (tid >= off) ? s[tid - off] : 0u;
        __syncthreads();
        s[tid] += t;
        __syncthreads();
    }
    g_hist[idx] = s[tid] - v;
    if (tid == 1023) g_bsum[blockIdx.x] = s[1023];
}

__global__ void scan2_kernel() {   // exclusive scan of block sums
    __shared__ u32 s[NB / 1024];
    const int tid = threadIdx.x;
    const u32 v = g_bsum[tid];
    s[tid] = v;
    __syncthreads();
    #pragma unroll
    for (int off = 1; off < NB / 1024; off <<= 1) {
        u32 t = (tid >= off) ? s[tid - off] : 0u;
        __syncthreads();
        s[tid] += t;
        __syncthreads();
    }
    g_bsum[tid] = s[tid] - v;
}

__global__ void scatter_kernel(const float* __restrict__ x, int n) {
    int i = blockIdx.x * blockDim.x + threadIdx.x;
    if (i >= n) return;
    const float xn0 = (x[3*i+0] + 1.0f) * 0.5f;
    const float xn1 = (x[3*i+1] + 1.0f) * 0.5f;
    const float xn2 = (x[3*i+2] + 1.0f) * 0.5f;
    const u32 key = bucket_key(xn0, xn1, xn2);
    // in-block-scanned base (from scan1) + block offset (from scan2), fused scan3
    const u32 pos = atomicAdd(&g_hist[key], 1u) + g_bsum[key >> 10];
    g_xs[pos] = make_float4(xn0, xn1, xn2, __int_as_float(i));
}

template<bool SORTED>
__global__ __launch_bounds__(256, 3) void field_kernel(
    const float* __restrict__ x,
    const float* __restrict__ table,
    const float* __restrict__ W0,
    const float* __restrict__ b0,
    const float* __restrict__ W1,
    const float* __restrict__ b1,
    const float* __restrict__ Wout,
    const float* __restrict__ bout,
    float* __restrict__ out,
    int n, LevelScales sc)
{
    __shared__ __align__(16) float sW0[NFEAT * HID];
    __shared__ __align__(16) float sW1[HID * HID];
    __shared__ __align__(16) float sB0[HID];
    __shared__ __align__(16) float sB1[HID];
    __shared__ __align__(16) float sWo[HID];
    __shared__ float sBo;

    const int tid = threadIdx.x;

    // re-zero histogram for the next graph replay (g_hist is not read by this kernel;
    // module load zero-init covers the very first call)
    if (SORTED) {
        const int gid = blockIdx.x * 256 + tid;
        if (gid < NB) g_hist[gid] = 0u;
    }

    for (int i = tid; i < NFEAT * HID; i += 256) sW0[i] = W0[i];
    for (int i = tid; i < HID * HID;   i += 256) sW1[i] = W1[i];
    if (tid < HID) { sB0[tid] = b0[tid]; sB1[tid] = b1[tid]; sWo[tid] = Wout[tid]; }
    if (tid == 0) sBo = bout[0];
    __syncthreads();

    const int i = blockIdx.x * 256 + tid;
    if (i >= n) return;

    float xn0, xn1, xn2;
    int oidx;
    if (SORTED) {
        const float4 p = g_xs[i];
        xn0 = p.x; xn1 = p.y; xn2 = p.z; oidx = __float_as_int(p.w);
    } else {
        xn0 = (x[3*i+0] + 1.0f) * 0.5f;
        xn1 = (x[3*i+1] + 1.0f) * 0.5f;
        xn2 = (x[3*i+2] + 1.0f) * 0.5f;
        oidx = i;
    }

    const u32 P1 = 2654435761u, P2 = 805459861u;
    const u32 msk = TSZ - 1u;

    // ---- h1 (packed pairs): h1 = b0 + xn0*W0[0,:] + xn1*W0[1,:] + xn2*W0[2,:] ----
    u64 h1p[HID/2];
    {
        const u64 x0p = pk2(xn0), x1p = pk2(xn1), x2p = pk2(xn2);
        #pragma unroll
        for (int q = 0; q < 8; ++q) {
            const ulonglong2 bb = *(const ulonglong2*)&sB0[4*q];
            const ulonglong2 w0 = *(const ulonglong2*)&sW0[0*HID + 4*q];
            const ulonglong2 w1 = *(const ulonglong2*)&sW0[1*HID + 4*q];
            const ulonglong2 w2 = *(const ulonglong2*)&sW0[2*HID + 4*q];
            h1p[2*q]   = fma2(x2p, w2.x, fma2(x1p, w1.x, fma2(x0p, w0.x, bb.x)));
            h1p[2*q+1] = fma2(x2p, w2.y, fma2(x1p, w1.y, fma2(x0p, w0.y, bb.y)));
        }
    }

    #pragma unroll
    for (int l = 0; l < NLVL; ++l) {
        const float s = sc.s[l];
        const float px = xn0 * s, py = xn1 * s, pz = xn2 * s;
        const float f0 = floorf(px), f1 = floorf(py), f2 = floorf(pz);
        const float wx = px - f0, wy = py - f1, wz = pz - f2;
        const u32 ix = (u32)f0, iy = (u32)f1, iz = (u32)f2;

        const u32 hx0 = ix,      hx1 = ix + 1u;
        const u32 hy0 = iy * P1, hy1 = (iy + 1u) * P1;
        const u32 hz0 = iz * P2, hz1 = (iz + 1u) * P2;

        const float2* __restrict__ tb = ((const float2*)table) + (size_t)l * TSZ;

        const float2 g000 = __ldg(tb + ((hx0 ^ hy0 ^ hz0) & msk));
        const float2 g100 = __ldg(tb + ((hx1 ^ hy0 ^ hz0) & msk));
        const float2 g010 = __ldg(tb + ((hx0 ^ hy1 ^ hz0) & msk));
        const float2 g110 = __ldg(tb + ((hx1 ^ hy1 ^ hz0) & msk));
        const float2 g001 = __ldg(tb + ((hx0 ^ hy0 ^ hz1) & msk));
        const float2 g101 = __ldg(tb + ((hx1 ^ hy0 ^ hz1) & msk));
        const float2 g011 = __ldg(tb + ((hx0 ^ hy1 ^ hz1) & msk));
        const float2 g111 = __ldg(tb + ((hx1 ^ hy1 ^ hz1) & msk));

        const float ux = 1.0f - wx, uy = 1.0f - wy, uz = 1.0f - wz;
        const float w000 = ux*uy*uz, w100 = wx*uy*uz, w010 = ux*wy*uz, w110 = wx*wy*uz;
        const float w001 = ux*uy*wz, w101 = wx*uy*wz, w011 = ux*wy*wz, w111 = wx*wy*wz;

        float a0 = w000 * g000.x, a1 = w000 * g000.y;
        a0 = fmaf(w100, g100.x, a0); a1 = fmaf(w100, g100.y, a1);
        a0 = fmaf(w010, g010.x, a0); a1 = fmaf(w010, g010.y, a1);
        a0 = fmaf(w110, g110.x, a0); a1 = fmaf(w110, g110.y, a1);
        a0 = fmaf(w001, g001.x, a0); a1 = fmaf(w001, g001.y, a1);
        a0 = fmaf(w101, g101.x, a0); a1 = fmaf(w101, g101.y, a1);
        a0 = fmaf(w011, g011.x, a0); a1 = fmaf(w011, g011.y, a1);
        a0 = fmaf(w111, g111.x, a0); a1 = fmaf(w111, g111.y, a1);

        // h1 += a0*W0[k,:] + a1*W0[k+1,:]  (packed over j-pairs; per-component order preserved)
        const int k = 3 + 2*l;
        const u64 a0p = pk2(a0), a1p = pk2(a1);
        const float* __restrict__ r0 = &sW0[k * HID];
        const float* __restrict__ r1 = &sW0[(k+1) * HID];
        #pragma unroll
        for (int q = 0; q < 8; ++q) {
            const ulonglong2 w0 = *(const ulonglong2*)(r0 + 4*q);
            const ulonglong2 w1 = *(const ulonglong2*)(r1 + 4*q);
            h1p[2*q]   = fma2(a1p, w1.x, fma2(a0p, w0.x, h1p[2*q]));
            h1p[2*q+1] = fma2(a1p, w1.y, fma2(a0p, w0.y, h1p[2*q+1]));
        }
    }

    // ---- ELU(h1), unpack to scalars ----
    float h1s[HID];
    #pragma unroll
    for (int q = 0; q < HID/2; ++q) {
        float a, b; unpk(h1p[q], a, b);
        h1s[2*q]   = (a > 0.0f) ? a : (__expf(a) - 1.0f);
        h1s[2*q+1] = (b > 0.0f) ? b : (__expf(b) - 1.0f);
    }

    // ---- h2 = elu(h1 @ W1 + b1), packed ----
    u64 h2p[HID/2];
    #pragma unroll
    for (int q = 0; q < 8; ++q) {
        const ulonglong2 bb = *(const ulonglong2*)&sB1[4*q];
        h2p[2*q] = bb.x; h2p[2*q+1] = bb.y;
    }
    #pragma unroll
    for (int k = 0; k < HID; ++k) {
        const u64 fp = pk2(h1s[k]);
        const float* __restrict__ row = &sW1[k * HID];
        #pragma unroll
        for (int q = 0; q < 8; ++q) {
            const ulonglong2 w = *(const ulonglong2*)(row + 4*q);
            h2p[2*q]   = fma2(fp, w.x, h2p[2*q]);
            h2p[2*q+1] = fma2(fp, w.y, h2p[2*q+1]);
        }
    }

    // ---- out = elu(h2) . Wout + bout (scalar, sequential order preserved) ----
    float acc = sBo;
    #pragma unroll
    for (int q = 0; q < HID/2; ++q) {
        float a, b; unpk(h2p[q], a, b);
        a = (a > 0.0f) ? a : (__expf(a) - 1.0f);
        b = (b > 0.0f) ? b : (__expf(b) - 1.0f);
        acc = fmaf(a, sWo[2*q], acc);
        acc = fmaf(b, sWo[2*q+1], acc);
    }

    out[oidx] = acc;
}

extern "C" void kernel_launch(void* const* d_in, const int* in_sizes, int n_in,
                              void* d_out, int out_size)
{
    const float* x     = (const float*)d_in[0];
    const float* table = (const float*)d_in[1];
    const float* W0    = (const float*)d_in[2];
    const float* b0    = (const float*)d_in[3];
    const float* W1    = (const float*)d_in[4];
    const float* b1    = (const float*)d_in[5];
    const float* Wout  = (const float*)d_in[6];
    const float* bout  = (const float*)d_in[7];
    float* out = (float*)d_out;

    const int n = in_sizes[0] / 3;

    LevelScales sc;
    const double B = exp(log(512.0 / 16.0) / 15.0);   // 2^(1/3)
    for (int l = 0; l < NLVL; ++l)
        sc.s[l] = (float)(16.0 * pow(B, (double)l) - 1.0);

    const int blocks = (n + 255) / 256;

    if (n <= MAXN) {
        hist_kernel<<<blocks, 256>>>(x, n);
        scan1_kernel<<<NB / 1024, 1024>>>();
        scan2_kernel<<<1, NB / 1024>>>();
        scatter_kernel<<<blocks, 256>>>(x, n);
        field_kernel<true><<<blocks, 256>>>(x, table, W0, b0, W1, b1, Wout, bout, out, n, sc);
    } else {
        field_kernel<false><<<blocks, 256>>>(x, table, W0, b0, W1, b1, Wout, bout, out, n, sc);
    }
}

// round 17
// speedup vs baseline: 1.0512x; 1.0146x over previous
#include <cuda_runtime.h>
#include <stdint.h>
#include <math.h>

// Field_64682207478165: instant-NGP hash-grid (L=16, T=2^19, F=2) + MLP 35->32->32->1 (ELU)
// Morton counting sort (64^3 buckets) for warp spatial locality + fused encode/MLP
// with packed f32x2 FFMA2 MLP. Sort: hist -> scan1 -> scan2 -> scatter (scan3 fused).
// Field kernel: grid-stride over 1332 blocks (weight smem load amortized 6x),
// re-zeroes the histogram for the next graph replay.

#define NLVL  16
#define TSZ   (1u << 19)
#define HID   32
#define NFEAT 35
#define NB    (1 << 18)      // 64^3 Morton buckets @ 1/128 granularity over [0.5,1)
#define MAXN  2097152
#define FIELD_BLOCKS 1332    // 148 SMs * 3 resident CTAs * 3 waves

typedef unsigned int u32;
typedef unsigned long long u64;

struct LevelScales { float s[NLVL]; };

__device__ float4 g_xs[MAXN];     // sorted (xn0, xn1, xn2, idx-as-bits)
__device__ u32    g_hist[NB];     // zero-initialized at load; re-zeroed by field_kernel
__device__ u32    g_bsum[NB / 1024];

// ---- packed f32x2 helpers ----
__device__ __forceinline__ u64 fma2(u64 a, u64 b, u64 c) {
    u64 d; asm("fma.rn.f32x2 %0, %1, %2, %3;" : "=l"(d) : "l"(a), "l"(b), "l"(c)); return d;
}
__device__ __forceinline__ u64 pk2(float f) {           // (f, f)
    u64 r; asm("mov.b64 %0, {%1, %1};" : "=l"(r) : "f"(f)); return r;
}
__device__ __forceinline__ void unpk(u64 v, float& a, float& b) {
    asm("mov.b64 {%0, %1}, %2;" : "=f"(a), "=f"(b) : "l"(v));
}

__device__ __forceinline__ u32 expand3(u32 v) {
    v &= 0x3FFu;
    v = (v | (v << 16)) & 0x30000FFu;
    v = (v | (v << 8))  & 0x300F00Fu;
    v = (v | (v << 4))  & 0x30C30C3u;
    v = (v | (v << 2))  & 0x9249249u;
    return v;
}

__device__ __forceinline__ u32 bucket_key(float xn0, float xn1, float xn2) {
    int ix = (int)((xn0 - 0.5f) * 128.0f);
    int iy = (int)((xn1 - 0.5f) * 128.0f);
    int iz = (int)((xn2 - 0.5f) * 128.0f);
    ix = min(63, max(0, ix)); iy = min(63, max(0, iy)); iz = min(63, max(0, iz));
    return expand3((u32)ix) | (expand3((u32)iy) << 1) | (expand3((u32)iz) << 2);
}

__global__ void hist_kernel(const float* __restrict__ x, int n) {
    int i = blockIdx.x * blockDim.x + threadIdx.x;
    if (i >= n) return;
    const float xn0 = (x[3*i+0] + 1.0f) * 0.5f;
    const float xn1 = (x[3*i+1] + 1.0f) * 0.5f;
    const float xn2 = (x[3*i+2] + 1.0f) * 0.5f;
    atomicAdd(&g_hist[bucket_key(xn0, xn1, xn2)], 1u);
}

__global__ void scan1_kernel() {   // in-block exclusive scan + block total
    __shared__ u32 s[1024];
    const int tid = threadIdx.x;
    const int idx = blockIdx.x * 1024 + tid;
    const u32 v = g_hist[idx];
    s[tid] = v;
    __syncthreads();
    #pragma unroll
    for (int off = 1; off < 1024; off <<= 1) {
        u32 t = (tid >= off) ? s[tid - off] : 0u;
        __syncthreads();
        s[tid] += t;
        __syncthreads();
    }
    g_hist[idx] = s[tid] - v;
    if (tid == 1023) g_bsum[blockIdx.x] = s[1023];
}

__global__ void scan2_kernel() {   // exclusive scan of block sums
    __shared__ u32 s[NB / 1024];
    const int tid = threadIdx.x;
    const u32 v = g_bsum[tid];
    s[tid] = v;
    __syncthreads();
    #pragma unroll
    for (int off = 1; off < NB / 1024; off <<= 1) {
        u32 t = (tid >= off) ? s[tid - off] : 0u;
        __syncthreads();
        s[tid] += t;
        __syncthreads();
    }
    g_bsum[tid] = s[tid] - v;
}

__global__ void scatter_kernel(const float* __restrict__ x, int n) {
    int i = blockIdx.x * blockDim.x + threadIdx.x;
    if (i >= n) return;
    const float xn0 = (x[3*i+0] + 1.0f) * 0.5f;
    const float xn1 = (x[3*i+1] + 1.0f) * 0.5f;
    const float xn2 = (x[3*i+2] + 1.0f) * 0.5f;
    const u32 key = bucket_key(xn0, xn1, xn2);
    // in-block-scanned base (from scan1) + block offset (from scan2), fused scan3
    const u32 pos = atomicAdd(&g_hist[key], 1u) + g_bsum[key >> 10];
    g_xs[pos] = make_float4(xn0, xn1, xn2, __int_as_float(i));
}

template<bool SORTED>
__global__ __launch_bounds__(256, 3) void field_kernel(
    const float* __restrict__ x,
    const float* __restrict__ table,
    const float* __restrict__ W0,
    const float* __restrict__ b0,
    const float* __restrict__ W1,
    const float* __restrict__ b1,
    const float* __restrict__ Wout,
    const float* __restrict__ bout,
    float* __restrict__ out,
    int n, LevelScales sc)
{
    __shared__ __align__(16) float sW0[NFEAT * HID];
    __shared__ __align__(16) float sW1[HID * HID];
    __shared__ __align__(16) float sB0[HID];
    __shared__ __align__(16) float sB1[HID];
    __shared__ __align__(16) float sWo[HID];
    __shared__ float sBo;

    const int tid = threadIdx.x;

    // re-zero histogram for the next graph replay (g_hist is not read by this kernel;
    // module load zero-init covers the very first call). FIELD_BLOCKS*256 > NB.
    if (SORTED) {
        const int gid = blockIdx.x * 256 + tid;
        if (gid < NB) g_hist[gid] = 0u;
    }

    for (int i = tid; i < NFEAT * HID; i += 256) sW0[i] = W0[i];
    for (int i = tid; i < HID * HID;   i += 256) sW1[i] = W1[i];
    if (tid < HID) { sB0[tid] = b0[tid]; sB1[tid] = b1[tid]; sWo[tid] = Wout[tid]; }
    if (tid == 0) sBo = bout[0];
    __syncthreads();

    const u32 P1 = 2654435761u, P2 = 805459861u;
    const u32 msk = TSZ - 1u;
    const int stride = gridDim.x * 256;

    for (int i = blockIdx.x * 256 + tid; i < n; i += stride) {

        float xn0, xn1, xn2;
        int oidx;
        if (SORTED) {
            const float4 p = g_xs[i];
            xn0 = p.x; xn1 = p.y; xn2 = p.z; oidx = __float_as_int(p.w);
        } else {
            xn0 = (x[3*i+0] + 1.0f) * 0.5f;
            xn1 = (x[3*i+1] + 1.0f) * 0.5f;
            xn2 = (x[3*i+2] + 1.0f) * 0.5f;
            oidx = i;
        }

        // ---- h1 (packed pairs): h1 = b0 + xn0*W0[0,:] + xn1*W0[1,:] + xn2*W0[2,:] ----
        u64 h1p[HID/2];
        {
            const u64 x0p = pk2(xn0), x1p = pk2(xn1), x2p = pk2(xn2);
            #pragma unroll
            for (int q = 0; q < 8; ++q) {
                const ulonglong2 bb = *(const ulonglong2*)&sB0[4*q];
                const ulonglong2 w0 = *(const ulonglong2*)&sW0[0*HID + 4*q];
                const ulonglong2 w1 = *(const ulonglong2*)&sW0[1*HID + 4*q];
                const ulonglong2 w2 = *(const ulonglong2*)&sW0[2*HID + 4*q];
                h1p[2*q]   = fma2(x2p, w2.x, fma2(x1p, w1.x, fma2(x0p, w0.x, bb.x)));
                h1p[2*q+1] = fma2(x2p, w2.y, fma2(x1p, w1.y, fma2(x0p, w0.y, bb.y)));
            }
        }

        #pragma unroll
        for (int l = 0; l < NLVL; ++l) {
            const float s = sc.s[l];
            const float px = xn0 * s, py = xn1 * s, pz = xn2 * s;
            const float f0 = floorf(px), f1 = floorf(py), f2 = floorf(pz);
            const float wx = px - f0, wy = py - f1, wz = pz - f2;
            const u32 ix = (u32)f0, iy = (u32)f1, iz = (u32)f2;

            const u32 hx0 = ix,      hx1 = ix + 1u;
            const u32 hy0 = iy * P1, hy1 = (iy + 1u) * P1;
            const u32 hz0 = iz * P2, hz1 = (iz + 1u) * P2;

            const float2* __restrict__ tb = ((const float2*)table) + (size_t)l * TSZ;

            const float2 g000 = __ldg(tb + ((hx0 ^ hy0 ^ hz0) & msk));
            const float2 g100 = __ldg(tb + ((hx1 ^ hy0 ^ hz0) & msk));
            const float2 g010 = __ldg(tb + ((hx0 ^ hy1 ^ hz0) & msk));
            const float2 g110 = __ldg(tb + ((hx1 ^ hy1 ^ hz0) & msk));
            const float2 g001 = __ldg(tb + ((hx0 ^ hy0 ^ hz1) & msk));
            const float2 g101 = __ldg(tb + ((hx1 ^ hy0 ^ hz1) & msk));
            const float2 g011 = __ldg(tb + ((hx0 ^ hy1 ^ hz1) & msk));
            const float2 g111 = __ldg(tb + ((hx1 ^ hy1 ^ hz1) & msk));

            const float ux = 1.0f - wx, uy = 1.0f - wy, uz = 1.0f - wz;
            const float w000 = ux*uy*uz, w100 = wx*uy*uz, w010 = ux*wy*uz, w110 = wx*wy*uz;
            const float w001 = ux*uy*wz, w101 = wx*uy*wz, w011 = ux*wy*wz, w111 = wx*wy*wz;

            float a0 = w000 * g000.x, a1 = w000 * g000.y;
            a0 = fmaf(w100, g100.x, a0); a1 = fmaf(w100, g100.y, a1);
            a0 = fmaf(w010, g010.x, a0); a1 = fmaf(w010, g010.y, a1);
            a0 = fmaf(w110, g110.x, a0); a1 = fmaf(w110, g110.y, a1);
            a0 = fmaf(w001, g001.x, a0); a1 = fmaf(w001, g001.y, a1);
            a0 = fmaf(w101, g101.x, a0); a1 = fmaf(w101, g101.y, a1);
            a0 = fmaf(w011, g011.x, a0); a1 = fmaf(w011, g011.y, a1);
            a0 = fmaf(w111, g111.x, a0); a1 = fmaf(w111, g111.y, a1);

            // h1 += a0*W0[k,:] + a1*W0[k+1,:]  (packed; per-component order preserved)
            const int k = 3 + 2*l;
            const u64 a0p = pk2(a0), a1p = pk2(a1);
            const float* __restrict__ r0 = &sW0[k * HID];
            const float* __restrict__ r1 = &sW0[(k+1) * HID];
            #pragma unroll
            for (int q = 0; q < 8; ++q) {
                const ulonglong2 w0 = *(const ulonglong2*)(r0 + 4*q);
                const ulonglong2 w1 = *(const ulonglong2*)(r1 + 4*q);
                h1p[2*q]   = fma2(a1p, w1.x, fma2(a0p, w0.x, h1p[2*q]));
                h1p[2*q+1] = fma2(a1p, w1.y, fma2(a0p, w0.y, h1p[2*q+1]));
            }
        }

        // ---- ELU(h1), unpack to scalars ----
        float h1s[HID];
        #pragma unroll
        for (int q = 0; q < HID/2; ++q) {
            float a, b; unpk(h1p[q], a, b);
            h1s[2*q]   = (a > 0.0f) ? a : (__expf(a) - 1.0f);
            h1s[2*q+1] = (b > 0.0f) ? b : (__expf(b) - 1.0f);
        }

        // ---- h2 = elu(h1 @ W1 + b1), packed ----
        u64 h2p[HID/2];
        #pragma unroll
        for (int q = 0; q < 8; ++q) {
            const ulonglong2 bb = *(const ulonglong2*)&sB1[4*q];
            h2p[2*q] = bb.x; h2p[2*q+1] = bb.y;
        }
        #pragma unroll
        for (int k = 0; k < HID; ++k) {
            const u64 fp = pk2(h1s[k]);
            const float* __restrict__ row = &sW1[k * HID];
            #pragma unroll
            for (int q = 0; q < 8; ++q) {
                const ulonglong2 w = *(const ulonglong2*)(row + 4*q);
                h2p[2*q]   = fma2(fp, w.x, h2p[2*q]);
                h2p[2*q+1] = fma2(fp, w.y, h2p[2*q+1]);
            }
        }

        // ---- out = elu(h2) . Wout + bout (scalar, sequential order preserved) ----
        float acc = sBo;
        #pragma unroll
        for (int q = 0; q < HID/2; ++q) {
            float a, b; unpk(h2p[q], a, b);
            a = (a > 0.0f) ? a : (__expf(a) - 1.0f);
            b = (b > 0.0f) ? b : (__expf(b) - 1.0f);
            acc = fmaf(a, sWo[2*q], acc);
            acc = fmaf(b, sWo[2*q+1], acc);
        }

        out[oidx] = acc;
    }
}

extern "C" void kernel_launch(void* const* d_in, const int* in_sizes, int n_in,
                              void* d_out, int out_size)
{
    const float* x     = (const float*)d_in[0];
    const float* table = (const float*)d_in[1];
    const float* W0    = (const float*)d_in[2];
    const float* b0    = (const float*)d_in[3];
    const float* W1    = (const float*)d_in[4];
    const float* b1    = (const float*)d_in[5];
    const float* Wout  = (const float*)d_in[6];
    const float* bout  = (const float*)d_in[7];
    float* out = (float*)d_out;

    const int n = in_sizes[0] / 3;

    LevelScales sc;
    const double B = exp(log(512.0 / 16.0) / 15.0);   // 2^(1/3)
    for (int l = 0; l < NLVL; ++l)
        sc.s[l] = (float)(16.0 * pow(B, (double)l) - 1.0);

    const int blocks = (n + 255) / 256;
    const int fblocks = (FIELD_BLOCKS < blocks) ? FIELD_BLOCKS : blocks;

    if (n <= MAXN) {
        hist_kernel<<<blocks, 256>>>(x, n);
        scan1_kernel<<<NB / 1024, 1024>>>();
        scan2_kernel<<<1, NB / 1024>>>();
        scatter_kernel<<<blocks, 256>>>(x, n);
        field_kernel<true><<<fblocks, 256>>>(x, table, W0, b0, W1, b1, Wout, bout, out, n, sc);
    } else {
        field_kernel<false><<<fblocks, 256>>>(x, table, W0, b0, W1, b1, Wout, bout, out, n, sc);
    }
}